// round 1
// baseline (speedup 1.0000x reference)
#include <cuda_runtime.h>
#include <math.h>

// ---------------------------------------------------------------------------
// SelfAttention: kv = X @ Wqk^T ; s = K0^T V^T * c ; a = softmax(s) ;
// q = a @ V ; out = perm(q) @ Wd^T + b
// B=4, T=2048, D=2048, H=16.  All fp32 SIMT tiled GEMMs (round-0 baseline).
// ---------------------------------------------------------------------------

#define TM 128
#define TN 128
#define TK 16
#define PAD 4

static const long KV_ELEMS = 4L * 2048 * 4096;   // 134 MB
static const long SQ_ELEMS = 4L * 2048 * 2048;   //  67 MB each

__device__ float g_kv[4L * 2048 * 4096];
__device__ float g_s [4L * 2048 * 2048];
__device__ float g_q [4L * 2048 * 2048];

// Row permutation for the final GEMM:
// out[b',t',:] = q[b, i, :] with h=t'&15, b=(t'>>4)&3, vh=(b'<<5)|(t'>>6),
// i=(h<<7)|vh.  Returns flat row into q viewed as (8192, 2048).
__device__ __forceinline__ long perm_row(int m) {
    int bp = m >> 11;
    int tp = m & 2047;
    int h  = tp & 15;
    int b  = (tp >> 4) & 3;
    int vh = (bp << 5) | (tp >> 6);
    int i  = (h << 7) | vh;
    return (long)b * 2048 + i;
}

// Generic tiled GEMM: C[m,n] = alpha * sum_k A[m,k]*B[n,k-ish] (+bias[n])
//   A element at A + m*sAm + k*sAk   (A_KC => sAk==1; else sAm==1)
//   B element at B + n*sBn + k*sBk   (B_KC => sBk==1; else sBn==1)
// All dims assumed multiples of 128 (TM/TN) and 16 (TK) — true for this problem.
template<bool A_KC, bool B_KC, bool PERM, bool BIAS>
__global__ __launch_bounds__(256, 2)
void gemm_tile(const float* __restrict__ A, const float* __restrict__ B,
               float* __restrict__ C, const float* __restrict__ bias,
               int M, int N, int K,
               long sAm, long sAk, long sBn, long sBk, long ldc,
               long bA, long bB, long bC, float alpha)
{
    __shared__ float As[TK][TM + PAD];
    __shared__ float Bs[TK][TN + PAD];

    A += (long)blockIdx.z * bA;
    B += (long)blockIdx.z * bB;
    C += (long)blockIdx.z * bC;

    const int tid = threadIdx.x;
    const int tx  = tid & 15;
    const int ty  = tid >> 4;
    const int rowBase = blockIdx.y * TM;
    const int colBase = blockIdx.x * TN;

    float acc[8][8];
#pragma unroll
    for (int i = 0; i < 8; ++i)
#pragma unroll
        for (int j = 0; j < 8; ++j) acc[i][j] = 0.f;

    for (int k0 = 0; k0 < K; k0 += TK) {
        // ---- load A tile into As[k][m] ----
        if (A_KC) {
#pragma unroll
            for (int r = 0; r < 2; ++r) {
                int s  = tid + r * 256;
                int m  = s >> 2;
                int kq = s & 3;
                long row = rowBase + m;
                if (PERM) row = perm_row((int)row);
                const float4 v = *(const float4*)(A + row * sAm + (long)(k0 + kq * 4));
                As[kq * 4 + 0][m] = v.x;
                As[kq * 4 + 1][m] = v.y;
                As[kq * 4 + 2][m] = v.z;
                As[kq * 4 + 3][m] = v.w;
            }
        } else {
#pragma unroll
            for (int r = 0; r < 2; ++r) {
                int s  = tid + r * 256;
                int k  = s >> 5;
                int mq = s & 31;
                const float4 v = *(const float4*)(A + (long)(k0 + k) * sAk
                                                  + (long)(rowBase + mq * 4));
                *(float4*)&As[k][mq * 4] = v;
            }
        }
        // ---- load B tile into Bs[k][n] ----
        if (B_KC) {
#pragma unroll
            for (int r = 0; r < 2; ++r) {
                int s  = tid + r * 256;
                int n  = s >> 2;
                int kq = s & 3;
                const float4 v = *(const float4*)(B + (long)(colBase + n) * sBn
                                                  + (long)(k0 + kq * 4));
                Bs[kq * 4 + 0][n] = v.x;
                Bs[kq * 4 + 1][n] = v.y;
                Bs[kq * 4 + 2][n] = v.z;
                Bs[kq * 4 + 3][n] = v.w;
            }
        } else {
#pragma unroll
            for (int r = 0; r < 2; ++r) {
                int s  = tid + r * 256;
                int k  = s >> 5;
                int nq = s & 31;
                const float4 v = *(const float4*)(B + (long)(k0 + k) * sBk
                                                  + (long)(colBase + nq * 4));
                *(float4*)&Bs[k][nq * 4] = v;
            }
        }
        __syncthreads();

#pragma unroll
        for (int kk = 0; kk < TK; ++kk) {
            float4 a0 = *(const float4*)&As[kk][ty * 4];
            float4 a1 = *(const float4*)&As[kk][ty * 4 + 64];
            float4 b0 = *(const float4*)&Bs[kk][tx * 4];
            float4 b1 = *(const float4*)&Bs[kk][tx * 4 + 64];
            float a[8] = {a0.x, a0.y, a0.z, a0.w, a1.x, a1.y, a1.z, a1.w};
            float b[8] = {b0.x, b0.y, b0.z, b0.w, b1.x, b1.y, b1.z, b1.w};
#pragma unroll
            for (int i = 0; i < 8; ++i)
#pragma unroll
                for (int j = 0; j < 8; ++j)
                    acc[i][j] = fmaf(a[i], b[j], acc[i][j]);
        }
        __syncthreads();
    }

    // ---- epilogue ----
#pragma unroll
    for (int ih = 0; ih < 2; ++ih) {
#pragma unroll
        for (int ii = 0; ii < 4; ++ii) {
            long r = (long)rowBase + ty * 4 + ii + ih * 64;
#pragma unroll
            for (int jh = 0; jh < 2; ++jh) {
                long c = (long)colBase + tx * 4 + jh * 64;
                float4 o;
                o.x = acc[ih * 4 + ii][jh * 4 + 0] * alpha;
                o.y = acc[ih * 4 + ii][jh * 4 + 1] * alpha;
                o.z = acc[ih * 4 + ii][jh * 4 + 2] * alpha;
                o.w = acc[ih * 4 + ii][jh * 4 + 3] * alpha;
                if (BIAS) {
                    const float4 bv = *(const float4*)(bias + c);
                    o.x += bv.x; o.y += bv.y; o.z += bv.z; o.w += bv.w;
                }
                *(float4*)(C + r * ldc + c) = o;
            }
        }
    }
}

// In-place softmax over rows of length 2048. One block (256 thr) per row.
__global__ __launch_bounds__(256)
void softmax2048(float* __restrict__ S)
{
    const long row = blockIdx.x;
    float* p = S + row * 2048;
    const int tid  = threadIdx.x;
    const int lane = tid & 31;
    const int wid  = tid >> 5;

    float v[8];
    float m = -1e30f;
#pragma unroll
    for (int j = 0; j < 8; ++j) {
        v[j] = p[tid + j * 256];
        m = fmaxf(m, v[j]);
    }
#pragma unroll
    for (int o = 16; o > 0; o >>= 1)
        m = fmaxf(m, __shfl_xor_sync(0xFFFFFFFFu, m, o));

    __shared__ float red[8];
    if (lane == 0) red[wid] = m;
    __syncthreads();
    float mm = red[0];
#pragma unroll
    for (int w = 1; w < 8; ++w) mm = fmaxf(mm, red[w]);
    __syncthreads();

    float sum = 0.f;
#pragma unroll
    for (int j = 0; j < 8; ++j) {
        v[j] = expf(v[j] - mm);
        sum += v[j];
    }
#pragma unroll
    for (int o = 16; o > 0; o >>= 1)
        sum += __shfl_xor_sync(0xFFFFFFFFu, sum, o);
    if (lane == 0) red[wid] = sum;
    __syncthreads();
    float tot = 0.f;
#pragma unroll
    for (int w = 0; w < 8; ++w) tot += red[w];

    const float inv = 1.f / tot;
#pragma unroll
    for (int j = 0; j < 8; ++j)
        p[tid + j * 256] = v[j] * inv;
}

extern "C" void kernel_launch(void* const* d_in, const int* in_sizes, int n_in,
                              void* d_out, int out_size)
{
    const float* x       = (const float*)d_in[0];   // (4, 2048, 2048)
    const float* w_qk    = (const float*)d_in[1];   // (4096, 2048)
    const float* w_dense = (const float*)d_in[2];   // (2048, 2048)
    const float* b_dense = (const float*)d_in[3];   // (2048,)
    float* out = (float*)d_out;                     // (4, 2048, 2048)

    float *kv, *s, *q;
    cudaGetSymbolAddress((void**)&kv, g_kv);
    cudaGetSymbolAddress((void**)&s,  g_s);
    cudaGetSymbolAddress((void**)&q,  g_q);

    const float scale = (float)(1.0 / sqrt((double)2048 * 2047 / 2.0));

    // 1) kv = X @ Wqk^T : M=8192, N=4096, K=2048 (NT)
    gemm_tile<true, true, false, false><<<dim3(4096 / TN, 8192 / TM, 1), 256>>>(
        x, w_qk, kv, nullptr, 8192, 4096, 2048,
        2048, 1,   2048, 1,   4096,  0, 0, 0, 1.f);

    // 2) s[b,i,j] = sum_m kv[b,m,i] * kv[b,j,2048+m] * scale  (per batch)
    gemm_tile<false, true, false, false><<<dim3(2048 / TN, 2048 / TM, 4), 256>>>(
        kv, kv + 2048, s, nullptr, 2048, 2048, 2048,
        1, 4096,   4096, 1,   2048,
        2048L * 4096, 2048L * 4096, 2048L * 2048, scale);

    // 3) a = softmax(s, axis=-1), in-place: 8192 rows of 2048
    softmax2048<<<8192, 256>>>(s);

    // 4) q[b,i,d] = sum_t a[b,i,t] * kv[b,t,2048+d]  (per batch, NN)
    gemm_tile<true, false, false, false><<<dim3(2048 / TN, 2048 / TM, 4), 256>>>(
        s, kv + 2048, q, nullptr, 2048, 2048, 2048,
        2048, 1,   1, 4096,   2048,
        2048L * 2048, 2048L * 4096, 2048L * 2048, 1.f);

    // 5) out = perm(q) @ Wd^T + b : M=8192, N=2048, K=2048 (NT + row perm + bias)
    gemm_tile<true, true, true, true><<<dim3(2048 / TN, 8192 / TM, 1), 256>>>(
        q, w_dense, out, b_dense, 8192, 2048, 2048,
        2048, 1,   2048, 1,   2048,  0, 0, 0, 1.f);
}

// round 2
// speedup vs baseline: 1.4041x; 1.4041x over previous
#include <cuda_runtime.h>
#include <math.h>
#include <stdint.h>

// ---------------------------------------------------------------------------
// SelfAttention on GB300 — round 2: all four GEMMs on tensor cores via
// tf32 mma.sync.m16n8k8 (fp32 accumulate), fragment-order shared memory,
// double-buffered tiles with register-staged prefetch.
// kv = X @ Wqk^T ; s = K0^T V^T * c ; a = softmax(s) ; q = a @ V ;
// out = perm(q) @ Wd^T + b.     B=4, T=2048, D=2048, H=16.
// ---------------------------------------------------------------------------

#define BM 128
#define BN 128
#define BK 32

__device__ float g_kv[4L * 2048 * 4096];
__device__ float g_s [4L * 2048 * 2048];
__device__ float g_q [4L * 2048 * 2048];

// out[b',t',:] = q[b,i,:]; h=t'&15, b=(t'>>4)&3, vh=(b'<<5)|(t'>>6), i=(h<<7)|vh
__device__ __forceinline__ long perm_row(long m) {
    int bp = (int)(m >> 11);
    int tp = (int)(m & 2047);
    int h  = tp & 15;
    int b  = (tp >> 4) & 3;
    int vh = (bp << 5) | (tp >> 6);
    int i  = (h << 7) | vh;
    return (long)b * 2048 + i;
}

__device__ __forceinline__ uint32_t f2tf32(float v) {
    uint32_t r;
    asm("cvt.rna.tf32.f32 %0, %1;" : "=r"(r) : "f"(v));
    return r;
}

__device__ __forceinline__ void mma_tf32(float c[4], const uint32_t a[4],
                                         const uint32_t b[2]) {
    asm volatile(
        "mma.sync.aligned.m16n8k8.row.col.f32.tf32.tf32.f32 "
        "{%0,%1,%2,%3}, {%4,%5,%6,%7}, {%8,%9}, {%0,%1,%2,%3};\n"
        : "+f"(c[0]), "+f"(c[1]), "+f"(c[2]), "+f"(c[3])
        : "r"(a[0]), "r"(a[1]), "r"(a[2]), "r"(a[3]), "r"(b[0]), "r"(b[1]));
}

// Fragment-order smem offsets.
// A region: [buf][slab(4)][m16blk(8)][lane(32)][areg(4)]  (4096 u32 / buf)
// B region: [buf][slab(4)][n8blk(16)][lane(32)][breg(2)]  (4096 u32 / buf)
__device__ __forceinline__ int a_off(int buf, int slab, int mb, int lane) {
    return (((buf * 4 + slab) * 8 + mb) * 32 + lane) * 4;
}
__device__ __forceinline__ int b_off(int buf, int slab, int nb, int lane) {
    return (((buf * 4 + slab) * 16 + nb) * 64) + lane * 2;
}

__device__ __forceinline__ void scatterA(uint32_t* sA, int buf, int m, int k, float v) {
    int slab = k >> 3, kk = k & 7;
    int tig = kk & 3, ah = kk >> 2;
    int g = m & 7, mh = (m >> 3) & 1, mb = m >> 4;
    sA[a_off(buf, slab, mb, g * 4 + tig) + ah * 2 + mh] = f2tf32(v);
}
__device__ __forceinline__ void scatterB(uint32_t* sB, int buf, int n, int k, float v) {
    int slab = k >> 3, kk = k & 7;
    int tig = kk & 3, bh = kk >> 2;
    int g = n & 7, nb = n >> 3;
    sB[b_off(buf, slab, nb, g * 4 + tig) + bh] = f2tf32(v);
}

// C[m,n] = alpha * sum_k A[m,k]*B[n,k] (+bias[n]).  Strides as in round 0.
template<bool A_KC, bool B_KC, bool PERM, bool BIAS>
__global__ __launch_bounds__(256, 1)
void gemm_tc(const float* __restrict__ A, const float* __restrict__ B,
             float* __restrict__ C, const float* __restrict__ bias,
             int K, long sAm, long sAk, long sBn, long sBk, long ldc,
             long bA, long bB, long bC, float alpha)
{
    extern __shared__ uint32_t smem[];
    uint32_t* sA = smem;          // 8192 u32 (2 bufs)
    uint32_t* sB = smem + 8192;   // 8192 u32

    A += (long)blockIdx.z * bA;
    B += (long)blockIdx.z * bB;
    C += (long)blockIdx.z * bC;

    const int tid  = threadIdx.x;
    const int lane = tid & 31;
    const int warp = tid >> 5;
    const int wm   = warp >> 2;   // 0..1
    const int wn   = warp & 3;    // 0..3
    const long rowBase = (long)blockIdx.y * BM;
    const long colBase = (long)blockIdx.x * BN;

    float acc[4][4][4];
#pragma unroll
    for (int i = 0; i < 4; ++i)
#pragma unroll
        for (int j = 0; j < 4; ++j)
#pragma unroll
            for (int c = 0; c < 4; ++c) acc[i][j][c] = 0.f;

    float4 va[4], vb[4];

    // ---- tile load: global -> registers ----
    auto loadTiles = [&](int k0) {
#pragma unroll
        for (int r = 0; r < 4; ++r) {
            int id = tid + r * 256;
            if (A_KC) {
                int m = id >> 3, kq = id & 7;
                long row = rowBase + m;
                if (PERM) row = perm_row(row);
                va[r] = *(const float4*)(A + row * sAm + (long)(k0 + kq * 4) * sAk);
            } else {
                int k = id >> 5, mq = id & 31;
                va[r] = *(const float4*)(A + (long)(k0 + k) * sAk
                                          + (rowBase + mq * 4) * sAm);
            }
        }
#pragma unroll
        for (int r = 0; r < 4; ++r) {
            int id = tid + r * 256;
            if (B_KC) {
                int n = id >> 3, kq = id & 7;
                vb[r] = *(const float4*)(B + (colBase + n) * sBn
                                          + (long)(k0 + kq * 4) * sBk);
            } else {
                int k = id >> 5, nq = id & 31;
                vb[r] = *(const float4*)(B + (long)(k0 + k) * sBk
                                          + (colBase + nq * 4) * sBn);
            }
        }
    };

    // ---- tile store: registers -> fragment-order smem (tf32) ----
    auto storeTiles = [&](int buf) {
#pragma unroll
        for (int r = 0; r < 4; ++r) {
            int id = tid + r * 256;
            float f[4] = {va[r].x, va[r].y, va[r].z, va[r].w};
            if (A_KC) {
                int m = id >> 3, kq = id & 7;
#pragma unroll
                for (int c = 0; c < 4; ++c) scatterA(sA, buf, m, kq * 4 + c, f[c]);
            } else {
                int k = id >> 5, mq = id & 31;
#pragma unroll
                for (int c = 0; c < 4; ++c) scatterA(sA, buf, mq * 4 + c, k, f[c]);
            }
        }
#pragma unroll
        for (int r = 0; r < 4; ++r) {
            int id = tid + r * 256;
            float f[4] = {vb[r].x, vb[r].y, vb[r].z, vb[r].w};
            if (B_KC) {
                int n = id >> 3, kq = id & 7;
#pragma unroll
                for (int c = 0; c < 4; ++c) scatterB(sB, buf, n, kq * 4 + c, f[c]);
            } else {
                int k = id >> 5, nq = id & 31;
#pragma unroll
                for (int c = 0; c < 4; ++c) scatterB(sB, buf, nq * 4 + c, k, f[c]);
            }
        }
    };

    auto compute = [&](int buf) {
#pragma unroll
        for (int slab = 0; slab < 4; ++slab) {
            uint32_t a[4][4];
            uint32_t b[4][2];
#pragma unroll
            for (int i = 0; i < 4; ++i) {
                uint4 t = *(const uint4*)&sA[a_off(buf, slab, wm * 4 + i, lane)];
                a[i][0] = t.x; a[i][1] = t.y; a[i][2] = t.z; a[i][3] = t.w;
            }
#pragma unroll
            for (int j = 0; j < 4; ++j) {
                uint2 t = *(const uint2*)&sB[b_off(buf, slab, wn * 4 + j, lane)];
                b[j][0] = t.x; b[j][1] = t.y;
            }
#pragma unroll
            for (int i = 0; i < 4; ++i)
#pragma unroll
                for (int j = 0; j < 4; ++j)
                    mma_tf32(acc[i][j], a[i], b[j]);
        }
    };

    // ---- main loop: double-buffered ----
    int buf = 0;
    loadTiles(0);
    storeTiles(0);
    __syncthreads();

    for (int k0 = 0; k0 < K; k0 += BK) {
        const bool has_next = (k0 + BK) < K;
        if (has_next) loadTiles(k0 + BK);
        compute(buf);
        if (has_next) {
            storeTiles(buf ^ 1);
            __syncthreads();
            buf ^= 1;
        }
    }

    // ---- epilogue ----
    const int g = lane >> 2, tig = lane & 3;
#pragma unroll
    for (int i = 0; i < 4; ++i) {
        long row0 = rowBase + wm * 64 + i * 16 + g;
        long row1 = row0 + 8;
#pragma unroll
        for (int j = 0; j < 4; ++j) {
            long col = colBase + wn * 32 + j * 8 + tig * 2;
            float2 lo, hi;
            lo.x = acc[i][j][0] * alpha;
            lo.y = acc[i][j][1] * alpha;
            hi.x = acc[i][j][2] * alpha;
            hi.y = acc[i][j][3] * alpha;
            if (BIAS) {
                const float2 bv = *(const float2*)(bias + col);
                lo.x += bv.x; lo.y += bv.y;
                hi.x += bv.x; hi.y += bv.y;
            }
            *(float2*)(C + row0 * ldc + col) = lo;
            *(float2*)(C + row1 * ldc + col) = hi;
        }
    }
}

// In-place softmax over rows of length 2048. One block (256 thr) per row.
__global__ __launch_bounds__(256)
void softmax2048(float* __restrict__ S)
{
    const long row = blockIdx.x;
    float* p = S + row * 2048;
    const int tid  = threadIdx.x;
    const int lane = tid & 31;
    const int wid  = tid >> 5;

    float v[8];
    float m = -1e30f;
#pragma unroll
    for (int j = 0; j < 8; ++j) {
        v[j] = p[tid + j * 256];
        m = fmaxf(m, v[j]);
    }
#pragma unroll
    for (int o = 16; o > 0; o >>= 1)
        m = fmaxf(m, __shfl_xor_sync(0xFFFFFFFFu, m, o));

    __shared__ float red[8];
    if (lane == 0) red[wid] = m;
    __syncthreads();
    float mm = red[0];
#pragma unroll
    for (int w = 1; w < 8; ++w) mm = fmaxf(mm, red[w]);
    __syncthreads();

    float sum = 0.f;
#pragma unroll
    for (int j = 0; j < 8; ++j) {
        v[j] = expf(v[j] - mm);
        sum += v[j];
    }
#pragma unroll
    for (int o = 16; o > 0; o >>= 1)
        sum += __shfl_xor_sync(0xFFFFFFFFu, sum, o);
    if (lane == 0) red[wid] = sum;
    __syncthreads();
    float tot = 0.f;
#pragma unroll
    for (int w = 0; w < 8; ++w) tot += red[w];

    const float inv = 1.f / tot;
#pragma unroll
    for (int j = 0; j < 8; ++j)
        p[tid + j * 256] = v[j] * inv;
}

extern "C" void kernel_launch(void* const* d_in, const int* in_sizes, int n_in,
                              void* d_out, int out_size)
{
    const float* x       = (const float*)d_in[0];   // (4, 2048, 2048)
    const float* w_qk    = (const float*)d_in[1];   // (4096, 2048)
    const float* w_dense = (const float*)d_in[2];   // (2048, 2048)
    const float* b_dense = (const float*)d_in[3];   // (2048,)
    float* out = (float*)d_out;                     // (4, 2048, 2048)

    float *kv, *s, *q;
    cudaGetSymbolAddress((void**)&kv, g_kv);
    cudaGetSymbolAddress((void**)&s,  g_s);
    cudaGetSymbolAddress((void**)&q,  g_q);

    const int SMEM = 65536;
    static int attr_done = 0;
    if (!attr_done) {
        cudaFuncSetAttribute(gemm_tc<true,  true,  false, false>,
                             cudaFuncAttributeMaxDynamicSharedMemorySize, SMEM);
        cudaFuncSetAttribute(gemm_tc<false, true,  false, false>,
                             cudaFuncAttributeMaxDynamicSharedMemorySize, SMEM);
        cudaFuncSetAttribute(gemm_tc<true,  false, false, false>,
                             cudaFuncAttributeMaxDynamicSharedMemorySize, SMEM);
        cudaFuncSetAttribute(gemm_tc<true,  true,  true,  true>,
                             cudaFuncAttributeMaxDynamicSharedMemorySize, SMEM);
        attr_done = 1;
    }

    const float scale = (float)(1.0 / sqrt((double)2048 * 2047 / 2.0));

    // 1) kv = X @ Wqk^T : M=8192, N=4096, K=2048
    gemm_tc<true, true, false, false><<<dim3(4096 / BN, 8192 / BM, 1), 256, SMEM>>>(
        x, w_qk, kv, nullptr, 2048,
        2048, 1,   2048, 1,   4096,  0, 0, 0, 1.f);

    // 2) s[b,i,j] = sum_m kv[b,m,i] * kv[b,j,2048+m] * scale
    gemm_tc<false, true, false, false><<<dim3(2048 / BN, 2048 / BM, 4), 256, SMEM>>>(
        kv, kv + 2048, s, nullptr, 2048,
        1, 4096,   4096, 1,   2048,
        2048L * 4096, 2048L * 4096, 2048L * 2048, scale);

    // 3) a = softmax(s, axis=-1), in-place: 8192 rows of 2048
    softmax2048<<<8192, 256>>>(s);

    // 4) q[b,i,d] = sum_t a[b,i,t] * kv[b,t,2048+d]
    gemm_tc<true, false, false, false><<<dim3(2048 / BN, 2048 / BM, 4), 256, SMEM>>>(
        s, kv + 2048, q, nullptr, 2048,
        2048, 1,   1, 4096,   2048,
        2048L * 2048, 2048L * 4096, 2048L * 2048, 1.f);

    // 5) out = perm(q) @ Wd^T + b : M=8192, N=2048, K=2048
    gemm_tc<true, true, true, true><<<dim3(2048 / BN, 8192 / BM, 1), 256, SMEM>>>(
        q, w_dense, out, b_dense, 2048,
        2048, 1,   2048, 1,   2048,  0, 0, 0, 1.f);
}

// round 3
// speedup vs baseline: 3.4529x; 2.4590x over previous
#include <cuda_runtime.h>
#include <math.h>
#include <stdint.h>

// ---------------------------------------------------------------------------
// SelfAttention — round 3: tf32 mma.sync + cp.async 3-stage pipeline,
// swizzled natural-layout smem, pre-rounded tf32 operands in HBM.
// kv = X @ Wqk^T ; s = K0^T V^T * c ; a = softmax(s) ; q = a @ V ;
// out = perm(q) @ Wd^T + b.     B=4, T=2048, D=2048, H=16.
// ---------------------------------------------------------------------------

#define BM 128
#define BN 128
#define BK 32
#define STAGES 3

__device__ float g_kv [4L * 2048 * 4096];
__device__ float g_s  [4L * 2048 * 2048];
__device__ float g_q  [4L * 2048 * 2048];
__device__ float g_x  [4L * 2048 * 2048];
__device__ float g_wqk[4096L * 2048];
__device__ float g_wd [2048L * 2048];

__device__ __forceinline__ long perm_row(long m) {
    int bp = (int)(m >> 11);
    int tp = (int)(m & 2047);
    int h  = tp & 15;
    int b  = (tp >> 4) & 3;
    int vh = (bp << 5) | (tp >> 6);
    int i  = (h << 7) | vh;
    return (long)b * 2048 + i;
}

__device__ __forceinline__ float f2tf32(float v) {
    uint32_t r;
    asm("cvt.rna.tf32.f32 %0, %1;" : "=r"(r) : "f"(v));
    return __uint_as_float(r);
}

__device__ __forceinline__ void mma_tf32(float c[4], const uint32_t a[4],
                                         const uint32_t b[2]) {
    asm volatile(
        "mma.sync.aligned.m16n8k8.row.col.f32.tf32.tf32.f32 "
        "{%0,%1,%2,%3}, {%4,%5,%6,%7}, {%8,%9}, {%0,%1,%2,%3};\n"
        : "+f"(c[0]), "+f"(c[1]), "+f"(c[2]), "+f"(c[3])
        : "r"(a[0]), "r"(a[1]), "r"(a[2]), "r"(a[3]), "r"(b[0]), "r"(b[1]));
}

__device__ __forceinline__ void cpasync16(uint32_t dst, const void* src) {
    asm volatile("cp.async.cg.shared.global [%0], [%1], 16;\n"
                 :: "r"(dst), "l"(src));
}
__device__ __forceinline__ void cp_commit() {
    asm volatile("cp.async.commit_group;\n");
}
template<int N>
__device__ __forceinline__ void cp_wait() {
    asm volatile("cp.async.wait_group %0;\n" :: "n"(N));
}

// word offsets within one 4096-word stage
// K-contig tile [x(128)][k(32)], 128B rows, 16B-chunk XOR with (x&7)
__device__ __forceinline__ int kc_off(int x, int k) {
    return x * 32 + ((((k >> 2) ^ (x & 7))) << 2) + (k & 3);
}
// M/N-contig tile [k(32)][x(128)], 512B rows, 16B-chunk XOR with (k&3)*2
__device__ __forceinline__ int mc_off(int x, int k) {
    return k * 128 + ((((x >> 2) ^ ((k & 3) << 1))) << 2) + (x & 3);
}

template<bool A_KC, bool B_KC, bool PERM, bool ROUND, bool BIAS>
__global__ __launch_bounds__(256, 2)
void gemm_tc(const float* __restrict__ A, const float* __restrict__ B,
             float* __restrict__ C, const float* __restrict__ bias,
             int K, long sAm, long sAk, long sBn, long sBk, long ldc,
             long bA, long bB, long bC, float alpha)
{
    extern __shared__ float smem[];
    const uint32_t smem_u32 = (uint32_t)__cvta_generic_to_shared(smem);

    A += (long)blockIdx.z * bA;
    B += (long)blockIdx.z * bB;
    C += (long)blockIdx.z * bC;

    const int tid  = threadIdx.x;
    const int lane = tid & 31;
    const int warp = tid >> 5;
    const int wm   = warp >> 2;     // 0..1
    const int wn   = warp & 3;      // 0..3
    const int g    = lane >> 2;     // 0..7
    const int tig  = lane & 3;      // 0..3
    const long rowBase = (long)blockIdx.y * BM;
    const long colBase = (long)blockIdx.x * BN;

    float acc[4][4][4];
#pragma unroll
    for (int i = 0; i < 4; ++i)
#pragma unroll
        for (int j = 0; j < 4; ++j)
#pragma unroll
            for (int c = 0; c < 4; ++c) acc[i][j][c] = 0.f;

    auto issueTile = [&](int t) {
        const int stage = t % STAGES;
        const int k0 = t * BK;
        const uint32_t aBase = smem_u32 + (uint32_t)(stage * 4096) * 4u;
        const uint32_t bBase = smem_u32 + (uint32_t)((STAGES + stage) * 4096) * 4u;
        if (A_KC) {
#pragma unroll
            for (int r = 0; r < 4; ++r) {
                int id = tid + r * 256;
                int x = id >> 3, ch = id & 7;
                long row = rowBase + x;
                if (PERM) row = perm_row(row);
                const float* src = A + row * sAm + (long)(k0 + ch * 4) * sAk;
                uint32_t dst = aBase + (uint32_t)(x * 32 + ((ch ^ (x & 7)) << 2)) * 4u;
                cpasync16(dst, src);
            }
        } else {
#pragma unroll
            for (int r = 0; r < 4; ++r) {
                int id = tid + r * 256;
                int k = id >> 5, c = id & 31;
                const float* src = A + (long)(k0 + k) * sAk + (rowBase + c * 4) * sAm;
                uint32_t dst = bBase; // placeholder avoid unused warn
                dst = aBase + (uint32_t)(k * 128 + ((c ^ ((k & 3) << 1)) << 2)) * 4u;
                cpasync16(dst, src);
            }
        }
        if (B_KC) {
#pragma unroll
            for (int r = 0; r < 4; ++r) {
                int id = tid + r * 256;
                int x = id >> 3, ch = id & 7;
                const float* src = B + (colBase + x) * sBn + (long)(k0 + ch * 4) * sBk;
                uint32_t dst = bBase + (uint32_t)(x * 32 + ((ch ^ (x & 7)) << 2)) * 4u;
                cpasync16(dst, src);
            }
        } else {
#pragma unroll
            for (int r = 0; r < 4; ++r) {
                int id = tid + r * 256;
                int k = id >> 5, c = id & 31;
                const float* src = B + (long)(k0 + k) * sBk + (colBase + c * 4) * sBn;
                uint32_t dst = bBase + (uint32_t)(k * 128 + ((c ^ ((k & 3) << 1)) << 2)) * 4u;
                cpasync16(dst, src);
            }
        }
    };

    auto compute = [&](int stage) {
        const float* sA = smem + stage * 4096;
        const float* sB = smem + (STAGES + stage) * 4096;
#pragma unroll
        for (int slab = 0; slab < 4; ++slab) {
            const int ks = slab * 8;
            uint32_t a[4][4];
            uint32_t b[4][2];
#pragma unroll
            for (int i = 0; i < 4; ++i) {
                const int m0 = wm * 64 + i * 16 + g;
                if (A_KC) {
                    a[i][0] = __float_as_uint(sA[kc_off(m0,     ks + tig)]);
                    a[i][1] = __float_as_uint(sA[kc_off(m0 + 8, ks + tig)]);
                    a[i][2] = __float_as_uint(sA[kc_off(m0,     ks + tig + 4)]);
                    a[i][3] = __float_as_uint(sA[kc_off(m0 + 8, ks + tig + 4)]);
                } else {
                    a[i][0] = __float_as_uint(sA[mc_off(m0,     ks + tig)]);
                    a[i][1] = __float_as_uint(sA[mc_off(m0 + 8, ks + tig)]);
                    a[i][2] = __float_as_uint(sA[mc_off(m0,     ks + tig + 4)]);
                    a[i][3] = __float_as_uint(sA[mc_off(m0 + 8, ks + tig + 4)]);
                }
            }
#pragma unroll
            for (int j = 0; j < 4; ++j) {
                const int n0 = wn * 32 + j * 8 + g;
                if (B_KC) {
                    b[j][0] = __float_as_uint(sB[kc_off(n0, ks + tig)]);
                    b[j][1] = __float_as_uint(sB[kc_off(n0, ks + tig + 4)]);
                } else {
                    b[j][0] = __float_as_uint(sB[mc_off(n0, ks + tig)]);
                    b[j][1] = __float_as_uint(sB[mc_off(n0, ks + tig + 4)]);
                }
            }
#pragma unroll
            for (int i = 0; i < 4; ++i)
#pragma unroll
                for (int j = 0; j < 4; ++j)
                    mma_tf32(acc[i][j], a[i], b[j]);
        }
    };

    const int nt = K / BK;
    issueTile(0); cp_commit();
    issueTile(1); cp_commit();

    for (int t = 0; t < nt; ++t) {
        cp_wait<1>();
        __syncthreads();
        if (t + 2 < nt) issueTile(t + 2);
        cp_commit();
        compute(t % STAGES);
    }

    // ---- epilogue ----
#pragma unroll
    for (int i = 0; i < 4; ++i) {
        long row0 = rowBase + wm * 64 + i * 16 + g;
        long row1 = row0 + 8;
#pragma unroll
        for (int j = 0; j < 4; ++j) {
            long col = colBase + wn * 32 + j * 8 + tig * 2;
            float2 lo, hi;
            lo.x = acc[i][j][0] * alpha;
            lo.y = acc[i][j][1] * alpha;
            hi.x = acc[i][j][2] * alpha;
            hi.y = acc[i][j][3] * alpha;
            if (BIAS) {
                const float2 bv = *(const float2*)(bias + col);
                lo.x += bv.x; lo.y += bv.y;
                hi.x += bv.x; hi.y += bv.y;
            }
            if (ROUND) {
                lo.x = f2tf32(lo.x); lo.y = f2tf32(lo.y);
                hi.x = f2tf32(hi.x); hi.y = f2tf32(hi.y);
            }
            *(float2*)(C + row0 * ldc + col) = lo;
            *(float2*)(C + row1 * ldc + col) = hi;
        }
    }
}

// elementwise tf32 rounding pre-pass (float4 grid-stride)
__global__ __launch_bounds__(256)
void round_tf32(const float* __restrict__ in, float* __restrict__ out, long n4)
{
    long i = (long)blockIdx.x * blockDim.x + threadIdx.x;
    long stride = (long)gridDim.x * blockDim.x;
    for (; i < n4; i += stride) {
        float4 v = ((const float4*)in)[i];
        v.x = f2tf32(v.x); v.y = f2tf32(v.y);
        v.z = f2tf32(v.z); v.w = f2tf32(v.w);
        ((float4*)out)[i] = v;
    }
}

// In-place softmax over rows of length 2048, output rounded to tf32.
__global__ __launch_bounds__(256)
void softmax2048(float* __restrict__ S)
{
    const long row = blockIdx.x;
    float* p = S + row * 2048;
    const int tid  = threadIdx.x;
    const int lane = tid & 31;
    const int wid  = tid >> 5;

    float v[8];
    float m = -1e30f;
#pragma unroll
    for (int j = 0; j < 8; ++j) {
        v[j] = p[tid + j * 256];
        m = fmaxf(m, v[j]);
    }
#pragma unroll
    for (int o = 16; o > 0; o >>= 1)
        m = fmaxf(m, __shfl_xor_sync(0xFFFFFFFFu, m, o));

    __shared__ float red[8];
    if (lane == 0) red[wid] = m;
    __syncthreads();
    float mm = red[0];
#pragma unroll
    for (int w = 1; w < 8; ++w) mm = fmaxf(mm, red[w]);
    __syncthreads();

    float sum = 0.f;
#pragma unroll
    for (int j = 0; j < 8; ++j) {
        v[j] = expf(v[j] - mm);
        sum += v[j];
    }
#pragma unroll
    for (int o = 16; o > 0; o >>= 1)
        sum += __shfl_xor_sync(0xFFFFFFFFu, sum, o);
    if (lane == 0) red[wid] = sum;
    __syncthreads();
    float tot = 0.f;
#pragma unroll
    for (int w = 0; w < 8; ++w) tot += red[w];

    const float inv = 1.f / tot;
#pragma unroll
    for (int j = 0; j < 8; ++j)
        p[tid + j * 256] = f2tf32(v[j] * inv);
}

extern "C" void kernel_launch(void* const* d_in, const int* in_sizes, int n_in,
                              void* d_out, int out_size)
{
    const float* x       = (const float*)d_in[0];   // (4, 2048, 2048)
    const float* w_qk    = (const float*)d_in[1];   // (4096, 2048)
    const float* w_dense = (const float*)d_in[2];   // (2048, 2048)
    const float* b_dense = (const float*)d_in[3];   // (2048,)
    float* out = (float*)d_out;                     // (4, 2048, 2048)

    float *kv, *s, *q, *rx, *rwqk, *rwd;
    cudaGetSymbolAddress((void**)&kv,   g_kv);
    cudaGetSymbolAddress((void**)&s,    g_s);
    cudaGetSymbolAddress((void**)&q,    g_q);
    cudaGetSymbolAddress((void**)&rx,   g_x);
    cudaGetSymbolAddress((void**)&rwqk, g_wqk);
    cudaGetSymbolAddress((void**)&rwd,  g_wd);

    const int SMEM = STAGES * 2 * 4096 * 4;   // 98304 B
    static int attr_done = 0;
    if (!attr_done) {
        cudaFuncSetAttribute(gemm_tc<true,  true,  false, true,  false>,
                             cudaFuncAttributeMaxDynamicSharedMemorySize, SMEM);
        cudaFuncSetAttribute(gemm_tc<false, true,  false, false, false>,
                             cudaFuncAttributeMaxDynamicSharedMemorySize, SMEM);
        cudaFuncSetAttribute(gemm_tc<true,  false, false, true,  false>,
                             cudaFuncAttributeMaxDynamicSharedMemorySize, SMEM);
        cudaFuncSetAttribute(gemm_tc<true,  true,  true,  false, true>,
                             cudaFuncAttributeMaxDynamicSharedMemorySize, SMEM);
        attr_done = 1;
    }

    const float scale = (float)(1.0 / sqrt((double)2048 * 2047 / 2.0));

    // 0) pre-round operands to tf32 precision
    round_tf32<<<1024, 256>>>(x,       rx,   (4L * 2048 * 2048) / 4);
    round_tf32<<<512,  256>>>(w_qk,    rwqk, (4096L * 2048) / 4);
    round_tf32<<<512,  256>>>(w_dense, rwd,  (2048L * 2048) / 4);

    // 1) kv = X @ Wqk^T : M=8192, N=4096, K=2048 (epilogue rounds kv to tf32)
    gemm_tc<true, true, false, true, false><<<dim3(4096 / BN, 8192 / BM, 1), 256, SMEM>>>(
        rx, rwqk, kv, nullptr, 2048,
        2048, 1,   2048, 1,   4096,  0, 0, 0, 1.f);

    // 2) s[b,i,j] = sum_m kv[b,m,i] * kv[b,j,2048+m] * scale   (fp32 out)
    gemm_tc<false, true, false, false, false><<<dim3(2048 / BN, 2048 / BM, 4), 256, SMEM>>>(
        kv, kv + 2048, s, nullptr, 2048,
        1, 4096,   4096, 1,   2048,
        2048L * 4096, 2048L * 4096, 2048L * 2048, scale);

    // 3) a = softmax(s), in-place, rounded to tf32
    softmax2048<<<8192, 256>>>(s);

    // 4) q[b,i,d] = sum_t a[b,i,t] * kv[b,t,2048+d]  (epilogue rounds q)
    gemm_tc<true, false, false, true, false><<<dim3(2048 / BN, 2048 / BM, 4), 256, SMEM>>>(
        s, kv + 2048, q, nullptr, 2048,
        2048, 1,   1, 4096,   2048,
        2048L * 2048, 2048L * 4096, 2048L * 2048, 1.f);

    // 5) out = perm(q) @ Wd^T + b : M=8192, N=2048, K=2048
    gemm_tc<true, true, true, false, true><<<dim3(2048 / BN, 8192 / BM, 1), 256, SMEM>>>(
        q, rwd, out, b_dense, 2048,
        2048, 1,   2048, 1,   2048,  0, 0, 0, 1.f);
}